// round 14
// baseline (speedup 1.0000x reference)
#include <cuda_runtime.h>

typedef unsigned int u32;
typedef unsigned short u16;
typedef unsigned long long u64;

#define NV 2048
#define NK 2051
#define NI 4096

// ---------------- device scratch (no allocations allowed) ----------------
__device__ float g_VuA[(size_t)NV * NV];
__device__ float g_KuA[(size_t)NV * NK];
__device__ float g_ViA[(size_t)NV * NI];
__device__ float g_KiA[5 * NI];
__device__ float g_ViP[(size_t)NV * NI];
__device__ float g_KiP[5 * NI];
__device__ double g_acc[5];

// ---------------- threefry2x32 (bit-exact with JAX) ----------------
__host__ __device__ __forceinline__ void tf2x32(u32 k0, u32 k1, u32 x0, u32 x1,
                                                u32 &o0, u32 &o1) {
  u32 k2 = k0 ^ k1 ^ 0x1BD11BDAu;
#define ROTL(x, r) (((x) << (r)) | ((x) >> (32 - (r))))
#define RND(r) { x0 += x1; x1 = ROTL(x1, r); x1 ^= x0; }
  x0 += k0; x1 += k1;
  RND(13) RND(15) RND(26) RND(6)  x0 += k1; x1 += k2 + 1u;
  RND(17) RND(29) RND(16) RND(24) x0 += k2; x1 += k0 + 2u;
  RND(13) RND(15) RND(26) RND(6)  x0 += k0; x1 += k1 + 3u;
  RND(17) RND(29) RND(16) RND(24) x0 += k1; x1 += k2 + 4u;
  RND(13) RND(15) RND(26) RND(6)  x0 += k2; x1 += k0 + 5u;
  o0 = x0; o1 = x1;
#undef RND
#undef ROTL
}

__device__ __forceinline__ u32 ford(float f) {  // total-order ascending key
  u32 u = __float_as_uint(f);
  return (u & 0x80000000u) ? ~u : (u | 0x80000000u);
}

// guess+gallop upper_bound: first idx with cdf[idx] > u. Exact for any g.
__device__ __forceinline__ int ubound_g(const float *cdf, int n, float u, int g) {
  int lo, hi;
  if (cdf[g] <= u) {
    int l = g, st = 8;
    while (l + st < n && cdf[l + st] <= u) { l += st; st <<= 2; }
    lo = l + 1;
    hi = min(l + st, n);
  } else {
    int h = g, st = 8;
    while (h - st >= 0 && cdf[h - st] > u) { h -= st; st <<= 2; }
    lo = max(h - st + 1, 0);
    hi = h;
  }
  while (lo < hi) { int m = (lo + hi) >> 1; if (cdf[m] <= u) lo = m + 1; else hi = m; }
  return lo;
}

__device__ __forceinline__ u32 f2tf32(float f) {
  u32 o;
  asm("cvt.rna.tf32.f32 %0, %1;" : "=r"(o) : "f"(f));
  return o;
}

__device__ __forceinline__ void mma_tf32(float c[4], u32 a0, u32 a1, u32 a2, u32 a3,
                                         u32 b0, u32 b1) {
  asm volatile(
      "mma.sync.aligned.m16n8k8.row.col.f32.tf32.tf32.f32 "
      "{%0,%1,%2,%3}, {%4,%5,%6,%7}, {%8,%9}, {%0,%1,%2,%3};"
      : "+f"(c[0]), "+f"(c[1]), "+f"(c[2]), "+f"(c[3])
      : "r"(a0), "r"(a1), "r"(a2), "r"(a3), "r"(b0), "r"(b1));
}

// ---------------- zero / finalize ----------------
__global__ void zero_kernel() { if (threadIdx.x < 5) g_acc[threadIdx.x] = 0.0; }

__global__ void fin_kernel(float *out) {
  if (threadIdx.x == 0) {
    out[0] = (float)g_acc[0];
    out[1] = (float)g_acc[1];
    out[2] = (float)g_acc[2];
    out[3] = (float)g_acc[3];
    out[4] = (float)(g_acc[4] / ((double)NI * (double)NI));
  }
}

// ---------------- transpose: in[R,Cc] -> out[Cc,R] ----------------
__global__ void transpose_kernel(const float *__restrict__ in, float *__restrict__ out,
                                 int R, int Cc) {
  __shared__ float t[32][33];
  int c0 = blockIdx.x * 32, r0 = blockIdx.y * 32;
  int x = threadIdx.x, y = threadIdx.y;
  for (int yy = y; yy < 32; yy += 8) {
    int r = r0 + yy, c = c0 + x;
    if (r < R && c < Cc) t[yy][x] = in[(size_t)r * Cc + c];
  }
  __syncthreads();
  for (int yy = y; yy < 32; yy += 8) {
    int c = c0 + yy, r = r0 + x;
    if (c < Cc && r < R) out[(size_t)c * R + r] = t[x][yy];
  }
}

// ---------------- TF32 TC GEMM: C[M,N] = A[M,64] B[N,64]^T ----------------
// 128x64 tile, 8 warps (4x2) x (32x32 each), K=64 one-shot, 3 blocks/SM.
#define GSTR 68
__global__ void __launch_bounds__(256, 3)
gemm_tc_kernel(const float *__restrict__ A, const float *__restrict__ B,
               float *C, int M, int N, int ldc,
               const float *__restrict__ sub, int ldsub) {
  extern __shared__ u32 smu[];
  u32 *As = smu;              // [128][GSTR] tf32 bits
  u32 *Bs = smu + 128 * GSTR; // [64][GSTR]
  int tid = threadIdx.x;
  int m0 = blockIdx.y * 128, n0 = blockIdx.x * 64;
  for (int idx = tid; idx < 128 * 16; idx += 256) {
    int row = idx >> 4, q = (idx & 15) << 2;
    int m = m0 + row;
    float4 v = (m < M) ? *(const float4 *)&A[(size_t)m * 64 + q]
                       : make_float4(0.f, 0.f, 0.f, 0.f);
    u32 *d = &As[row * GSTR + q];
    d[0] = f2tf32(v.x); d[1] = f2tf32(v.y); d[2] = f2tf32(v.z); d[3] = f2tf32(v.w);
  }
  for (int idx = tid; idx < 64 * 16; idx += 256) {
    int row = idx >> 4, q = (idx & 15) << 2;
    int n = n0 + row;
    float4 v = (n < N) ? *(const float4 *)&B[(size_t)n * 64 + q]
                       : make_float4(0.f, 0.f, 0.f, 0.f);
    u32 *d = &Bs[row * GSTR + q];
    d[0] = f2tf32(v.x); d[1] = f2tf32(v.y); d[2] = f2tf32(v.z); d[3] = f2tf32(v.w);
  }
  __syncthreads();
  int wid = tid >> 5, lane = tid & 31;
  int warpM = wid >> 1, warpN = wid & 1;       // 4 x 2 warps
  int m0w = warpM * 32, n0w = warpN * 32;
  int gid = lane >> 2, tig = lane & 3;
  float acc[2][4][4];
#pragma unroll
  for (int mi = 0; mi < 2; mi++)
#pragma unroll
    for (int ni = 0; ni < 4; ni++)
#pragma unroll
      for (int q = 0; q < 4; q++) acc[mi][ni][q] = 0.f;
#pragma unroll
  for (int kk = 0; kk < 64; kk += 8) {
    u32 a[2][4], b[4][2];
#pragma unroll
    for (int mi = 0; mi < 2; mi++) {
      int row = m0w + mi * 16 + gid;
      a[mi][0] = As[row * GSTR + kk + tig];
      a[mi][1] = As[(row + 8) * GSTR + kk + tig];
      a[mi][2] = As[row * GSTR + kk + tig + 4];
      a[mi][3] = As[(row + 8) * GSTR + kk + tig + 4];
    }
#pragma unroll
    for (int ni = 0; ni < 4; ni++) {
      int brow = n0w + ni * 8 + gid;
      b[ni][0] = Bs[brow * GSTR + kk + tig];
      b[ni][1] = Bs[brow * GSTR + kk + tig + 4];
    }
#pragma unroll
    for (int mi = 0; mi < 2; mi++)
#pragma unroll
      for (int ni = 0; ni < 4; ni++)
        mma_tf32(acc[mi][ni], a[mi][0], a[mi][1], a[mi][2], a[mi][3],
                 b[ni][0], b[ni][1]);
  }
  if (sub == nullptr) {
#pragma unroll
    for (int mi = 0; mi < 2; mi++) {
      int r0 = m0 + m0w + mi * 16 + gid;
#pragma unroll
      for (int ni = 0; ni < 4; ni++) {
        int c0 = n0 + n0w + ni * 8 + 2 * tig;
        if (r0 < M) {
          if (c0 < N) C[(size_t)r0 * ldc + c0] = acc[mi][ni][0];
          if (c0 + 1 < N) C[(size_t)r0 * ldc + c0 + 1] = acc[mi][ni][1];
        }
        if (r0 + 8 < M) {
          if (c0 < N) C[(size_t)(r0 + 8) * ldc + c0] = acc[mi][ni][2];
          if (c0 + 1 < N) C[(size_t)(r0 + 8) * ldc + c0 + 1] = acc[mi][ni][3];
        }
      }
    }
  } else {
    // fused |C - sub| path: only called with full tiles (M,N multiples of tile)
    float s = 0.0f;
#pragma unroll
    for (int mi = 0; mi < 2; mi++) {
      int r0 = m0 + m0w + mi * 16 + gid;
#pragma unroll
      for (int ni = 0; ni < 4; ni++) {
        int c0 = n0 + n0w + ni * 8 + 2 * tig;
        float2 s0v = *(const float2 *)&sub[(size_t)r0 * ldsub + c0];
        float2 s1v = *(const float2 *)&sub[(size_t)(r0 + 8) * ldsub + c0];
        s += fabsf(acc[mi][ni][0] - s0v.x);
        s += fabsf(acc[mi][ni][1] - s0v.y);
        s += fabsf(acc[mi][ni][2] - s1v.x);
        s += fabsf(acc[mi][ni][3] - s1v.y);
      }
    }
    for (int o = 16; o > 0; o >>= 1) s += __shfl_down_sync(0xffffffffu, s, o);
    __shared__ double red[8];
    if (lane == 0) red[wid] = (double)s;
    __syncthreads();
    if (tid == 0) {
      double t = 0.0;
#pragma unroll
      for (int w = 0; w < 8; w++) t += red[w];
      atomicAdd(&g_acc[4], t);
    }
  }
}

// ---------------- merged contrast loss; one block per row -----------------
// All four losses in ONE launch. NB=4096 buckets (1 key/bucket for uniform).
struct CtrArgs {
  const float *padj; const float *nsrc; const float *px; const float *nx;
  int ldp, Cp, ldn, Cn, nmode, ldpx, ldnx, K;
  float bScale, bBias;
  u32 kp0, kp1, kn0, kn1;
  int accIdx;
};

struct CtrSm {
  static constexpr int MAXC = 4096;
  static constexpr int NB = 4096;
  float pRow[MAXC];  // input row; becomes X row after cdf phase (stageX)
  int bStart[NB];    // buckets during sort; qtab hints afterwards
  union {
    struct { u32 k[MAXC]; u16 i[MAXC]; } slot;  // i survives cdf/negList writes
    float cdf[MAXC];
    int negList[MAXC];
  } u;
  double warpS[16];
};

__device__ __forceinline__ void ctr_body(const CtrArgs &A, int r, CtrSm &sm) {
  constexpr int ITEMS = 8;
  constexpr int NB = CtrSm::NB;
  const int nt = 512;
  int tid = threadIdx.x;
  int lane = tid & 31, wid = tid >> 5;
  const float *padj = A.padj;
  int ldp = A.ldp, Cp = A.Cp, Cn = A.Cn, nmode = A.nmode;
  __shared__ int cnt[2];
  __shared__ int wSi[16];
  __shared__ float sN[8];
  if (tid < 2) cnt[tid] = 0;
  if (nmode == 2 && tid < Cn)
    sN[tid] = 1.f - (A.nsrc[(size_t)r * A.ldn + tid] > 0.f ? 1.f : 0.f);
  __syncthreads();
  int pc = 0, nc = 0;
  for (int c = tid; c < Cp; c += nt) {
    float p = padj[(size_t)r * ldp + c];
    sm.pRow[c] = p;
    if (p > 0.f) pc++;
    if (nmode == 0) { if (p <= 0.f && c != r) nc++; }
    else if (nmode == 1) { if (1.f - p > 0.f) nc++; }
  }
  if (nmode == 2 && tid < Cn && sN[tid] > 0.f) nc++;
  for (int o = 16; o > 0; o >>= 1) {
    pc += __shfl_down_sync(0xffffffffu, pc, o);
    nc += __shfl_down_sync(0xffffffffu, nc, o);
  }
  if (lane == 0) { atomicAdd(&cnt[0], pc); atomicAdd(&cnt[1], nc); }
  __syncthreads();
  int pcnt = cnt[0], ncnt = cnt[1], num = min(pcnt, ncnt);
  if (num == 0) return;
  bool brA = (pcnt <= ncnt);
  int Cs = brA ? Cp : Cn;   // argsorted side width
  int Cw = brA ? Cn : Cp;   // sampled side width
  u32 s0 = brA ? A.kn0 : A.kp0, s1 = brA ? A.kn1 : A.kp1;
  const bool intA = brA && (nmode == 0);  // sampled weights in {1,0}
  const bool stageX = (A.px == A.nx) && (A.ldpx == A.ldnx);

  auto nval = [&](int c) -> float {
    if (nmode == 0) return 1.f - (sm.pRow[c] > 0.f ? 1.f : 0.f) - (c == r ? 1.f : 0.f);
    if (nmode == 1) return 1.f - sm.pRow[c];
    return sN[c];
  };

  int posOff = Cs - num;
  if (Cs <= 32) {  // tiny-sort fast path (Ku branch-B: Cs == 3)
    if (tid < Cs) {
      float v = brA ? sm.pRow[tid] : nval(tid);
      u64 mine = (((u64)ford(v)) << 12) | (u32)tid;
      int rank = 0;
      for (int c = 0; c < Cs; c++) {
        float w = brA ? sm.pRow[c] : nval(c);
        u64 other = (((u64)ford(w)) << 12) | (u32)c;
        if (other < mine) rank++;
      }
      sm.u.slot.i[rank] = (u16)tid;
    }
    __syncthreads();
  } else if (!brA && nmode == 0) {
    // branch-B ternary no-sort: top-num of {1,0,-1} stable ascending ==
    // indices with (p<=0 && c!=r) in ascending index order.
    int base = tid * ITEMS, myc = 0;
    u16 loc[ITEMS];
#pragma unroll
    for (int i = 0; i < ITEMS; i++) {
      int c = base + i;
      if (c < Cs && sm.pRow[c] <= 0.f && c != r) loc[myc++] = (u16)c;
    }
    int inc = myc;
#pragma unroll
    for (int o = 1; o < 32; o <<= 1) {
      int t = __shfl_up_sync(0xffffffffu, inc, o);
      if (lane >= o) inc += t;
    }
    if (lane == 31) wSi[wid] = inc;
    __syncthreads();
    if (tid < 16) {
      int w = wSi[tid];
#pragma unroll
      for (int o = 1; o < 16; o <<= 1) {
        int t = __shfl_up_sync(0x0000ffffu, w, o);
        if (tid >= o) w += t;
      }
      wSi[tid] = w;
    }
    __syncthreads();
    int off = (wid ? wSi[wid - 1] : 0) + inc - myc;
    for (int t = 0; t < myc; t++) sm.u.slot.i[off + t] = loc[t];
    __syncthreads();
    posOff = 0;
  } else {
    // ---- bucket argsort of the sorted side ----
    for (int b = tid; b < NB; b += nt) sm.bStart[b] = 0;
    __syncthreads();
    for (int c = tid; c < Cs; c += nt) {
      float v = brA ? sm.pRow[c] : nval(c);
      int b = min(max((int)fmaf(v, A.bScale, A.bBias), 0), NB - 1);
      atomicAdd(&sm.bStart[b], 1);
    }
    __syncthreads();
    {  // exclusive scan of bucket counts
      int base = tid * (NB / nt);
      int it[NB / nt], s = 0;
#pragma unroll
      for (int i = 0; i < NB / nt; i++) { it[i] = sm.bStart[base + i]; s += it[i]; }
      int inc = s;
#pragma unroll
      for (int o = 1; o < 32; o <<= 1) {
        int t = __shfl_up_sync(0xffffffffu, inc, o);
        if (lane >= o) inc += t;
      }
      if (lane == 31) wSi[wid] = inc;
      __syncthreads();
      if (tid < 16) {
        int w = wSi[tid];
#pragma unroll
        for (int o = 1; o < 16; o <<= 1) {
          int t = __shfl_up_sync(0x0000ffffu, w, o);
          if (tid >= o) w += t;
        }
        wSi[tid] = w;
      }
      __syncthreads();
      int run = (wid ? wSi[wid - 1] : 0) + inc - s;
#pragma unroll
      for (int i = 0; i < NB / nt; i++) { int c0 = it[i]; sm.bStart[base + i] = run; run += c0; }
      __syncthreads();
    }
    for (int c = tid; c < Cs; c += nt) {
      float v = brA ? sm.pRow[c] : nval(c);
      int b = min(max((int)fmaf(v, A.bScale, A.bBias), 0), NB - 1);
      int slot = atomicAdd(&sm.bStart[b], 1);
      sm.u.slot.k[slot] = ford(v);
      sm.u.slot.i[slot] = (u16)c;
    }
    __syncthreads();
    // per-bucket exact stable insertion sort on (ford<<16 | idx)
    for (int b = tid; b < NB; b += nt) {
      int s0b = b ? sm.bStart[b - 1] : 0;
      int e0b = sm.bStart[b];
      for (int x = s0b + 1; x < e0b; x++) {
        u32 kx = sm.u.slot.k[x];
        u16 ix = sm.u.slot.i[x];
        u64 cx = (((u64)kx) << 16) | ix;
        int y = x - 1;
        while (y >= s0b) {
          u64 cy = (((u64)sm.u.slot.k[y]) << 16) | sm.u.slot.i[y];
          if (cy <= cx) break;
          sm.u.slot.k[y + 1] = sm.u.slot.k[y];
          sm.u.slot.i[y + 1] = sm.u.slot.i[y];
          y--;
        }
        sm.u.slot.k[y + 1] = kx;
        sm.u.slot.i[y + 1] = ix;
      }
    }
    __syncthreads();
  }

  float total;
  int *qtab = sm.bStart;  // bStart dead after sort; NB entries available
  if (intA) {
    // Stable compaction of {c : weight==1} into negList (aliases dead keys).
    int base = tid * ITEMS, myc = 0;
    int loc[ITEMS];
#pragma unroll
    for (int i = 0; i < ITEMS; i++) {
      int c = base + i;
      if (c < Cw && c < Cp && sm.pRow[c] <= 0.f && c != r) loc[myc++] = c;
    }
    int inc = myc;
#pragma unroll
    for (int o = 1; o < 32; o <<= 1) {
      int t = __shfl_up_sync(0xffffffffu, inc, o);
      if (lane >= o) inc += t;
    }
    if (lane == 31) wSi[wid] = inc;
    __syncthreads();
    if (tid < 16) {
      int w = wSi[tid];
#pragma unroll
      for (int o = 1; o < 16; o <<= 1) {
        int t = __shfl_up_sync(0x0000ffffu, w, o);
        if (tid >= o) w += t;
      }
      wSi[tid] = w;
    }
    __syncthreads();
    int off = (wid ? wSi[wid - 1] : 0) + inc - myc;
    for (int t = 0; t < myc; t++) sm.u.negList[off + t] = loc[t];
    total = (float)ncnt;
    __syncthreads();
  } else {
    for (int b = tid; b < CtrSm::NB; b += nt) qtab[b] = (int)(((long long)b * Cw) >> 12);
    int ch = (Cw + nt - 1) / nt, b0 = tid * ch, e0 = min(Cw, b0 + ch);
    double s = 0.0;
    for (int i = b0; i < e0; i++) {
      float v = brA ? nval(i) : sm.pRow[i];
      if (v > 0.f) s += (double)v;
    }
    double inc = s;
#pragma unroll
    for (int o = 1; o < 32; o <<= 1) {
      double t = __shfl_up_sync(0xffffffffu, inc, o);
      if (lane >= o) inc += t;
    }
    if (lane == 31) sm.warpS[wid] = inc;
    __syncthreads();
    if (tid < 16) {
      double w = sm.warpS[tid];
#pragma unroll
      for (int o = 1; o < 16; o <<= 1) {
        double t = __shfl_up_sync(0x0000ffffu, w, o);
        if (tid >= o) w += t;
      }
      sm.warpS[tid] = w;
    }
    __syncthreads();
    float totF = (float)sm.warpS[15];
    float qs = 4096.0f / totF;
    double run = (wid ? sm.warpS[wid - 1] : 0.0) + (inc - s);  // exclusive prefix
    for (int i = b0; i < e0; i++) {
      float v = brA ? nval(i) : sm.pRow[i];
      if (v > 0.f) run += (double)v;
      float cv = (float)run;
      sm.u.cdf[i] = cv;
      qtab[min((int)(cv * qs), 4095)] = i;  // hint only; races benign
    }
    __syncthreads();
    total = sm.u.cdf[Cw - 1];
  }

  // pRow now dead -> stage X row into its smem (px==nx cases: Vu/Vi/Ki).
  if (stageX) {
    const float *xsrc = A.px + (size_t)r * A.ldpx;
    for (int c = tid; c < Cp; c += nt) sm.pRow[c] = xsrc[c];
  }
  __syncthreads();

  const float *pxr = A.px + (size_t)r * A.ldpx;
  const float *nxr = A.nx + (size_t)r * A.ldnx;
  double loc = 0.0;
  for (int j = tid; j < num; j += nt) {
    u32 a, b;
    tf2x32(s0, s1, 0u, (u32)(r * A.K + j), a, b);
    u32 bits = a ^ b;
    float f = __uint_as_float((bits >> 9) | 0x3f800000u) - 1.0f;
    float u = f * total;
    int samp;
    if (intA) {
      samp = sm.u.negList[min((int)u, ncnt - 1)];
    } else {
      int bin = min((int)(f * 4096.0f), 4095);
      int g = min(max(qtab[bin], 0), Cw - 1);
      samp = min(ubound_g(sm.u.cdf, Cw, u, g), Cw - 1);
    }
    int pos = (int)sm.u.slot.i[posOff + j];
    float xn, xp;
    if (stageX) {
      xn = sm.pRow[brA ? samp : pos];
      xp = sm.pRow[brA ? pos : samp];
    } else {
      xn = brA ? nxr[samp] : nxr[pos];
      xp = brA ? pxr[pos] : pxr[samp];
    }
    float t = xn - xp + 1.0f;
    if (t > 0.f) loc += (double)t;
  }
#pragma unroll
  for (int o = 16; o > 0; o >>= 1) loc += __shfl_down_sync(0xffffffffu, loc, o);
  if (lane == 0) sm.warpS[wid] = loc;
  __syncthreads();
  if (tid == 0) {
    double s = 0.0;
#pragma unroll
    for (int w = 0; w < 16; w++) s += sm.warpS[w];
    atomicAdd(&g_acc[A.accIdx], s / (double)num);
  }
}

__global__ void __launch_bounds__(512, 4)
contrast_merged(CtrArgs A0, CtrArgs A1, CtrArgs A2, CtrArgs A3,
                int e0, int e1, int e2) {
  extern __shared__ char smraw[];
  CtrSm &sm = *reinterpret_cast<CtrSm *>(smraw);
  int bid = blockIdx.x;
  if (bid < e0)       ctr_body(A0, bid, sm);
  else if (bid < e1)  ctr_body(A1, bid - e0, sm);
  else if (bid < e2)  ctr_body(A2, bid - e1, sm);
  else                ctr_body(A3, bid - e2, sm);
}

// ---------------- launch ----------------
extern "C" void kernel_launch(void* const* d_in, const int* in_sizes, int n_in,
                              void* d_out, int out_size) {
  const float *KUU = (const float *)d_in[0];
  const float *VUU = (const float *)d_in[1];
  const float *Vuser = (const float *)d_in[2];
  const float *Vitem = (const float *)d_in[3];
  const float *Kuser = (const float *)d_in[4];
  const float *Kitem = (const float *)d_in[5];
  const float *pref = (const float *)d_in[7];
  const float *Vpref = (const float *)d_in[8];
  const float *structure = (const float *)d_in[9];
  float *out = (float *)d_out;

  float *VuA, *KuA, *ViA, *KiA, *ViP, *KiP;
  cudaGetSymbolAddress((void **)&VuA, g_VuA);
  cudaGetSymbolAddress((void **)&KuA, g_KuA);
  cudaGetSymbolAddress((void **)&ViA, g_ViA);
  cudaGetSymbolAddress((void **)&KiA, g_KiA);
  cudaGetSymbolAddress((void **)&ViP, g_ViP);
  cudaGetSymbolAddress((void **)&KiP, g_KiP);

  // JAX key chain: key(42) -> split 4 -> per-loss split 2 (kp, kn)
  u32 ks[4][2], kp[4][2], kn[4][2];
  for (int i = 0; i < 4; i++) tf2x32(0u, 42u, 0u, (u32)i, ks[i][0], ks[i][1]);
  for (int i = 0; i < 4; i++) {
    tf2x32(ks[i][0], ks[i][1], 0u, 0u, kp[i][0], kp[i][1]);
    tf2x32(ks[i][0], ks[i][1], 0u, 1u, kn[i][0], kn[i][1]);
  }

  const int gemmSm = (128 + 64) * GSTR * 4;  // 52224
  const int ctrSm = (int)sizeof(CtrSm);
  cudaFuncSetAttribute(gemm_tc_kernel, cudaFuncAttributeMaxDynamicSharedMemorySize, gemmSm);
  cudaFuncSetAttribute(contrast_merged, cudaFuncAttributeMaxDynamicSharedMemorySize, ctrSm);

  // segment args: Vi, Vu, Ku, Ki (NB=4096 buckets)
  CtrArgs aVi = {ViP, ViP, ViA, ViA, NI, NI, NI, NI, 1, NI, NI, NI,
                 4096.0f, 0.0f, kp[2][0], kp[2][1], kn[2][0], kn[2][1], 2};
  CtrArgs aVu = {VUU, VUU, VuA, VuA, NV, NV, NV, NV, 0, NV, NV, 2048,
                 512.0f, 2048.0f, kp[0][0], kp[0][1], kn[0][0], kn[0][1], 0};
  CtrArgs aKu = {KUU, KUU + 2048, KuA, KuA + 2048, NK, 2048, NK, 3, 2, NK, NK, 3,
                 512.0f, 2048.0f, kp[1][0], kp[1][1], kn[1][0], kn[1][1], 1};
  CtrArgs aKi = {KiP, KiP, KiA, KiA, NI, NI, NI, NI, 1, NI, NI, NI,
                 4096.0f, 0.0f, kp[3][0], kp[3][1], kn[3][0], kn[3][1], 3};
  const int nBlocks = 2048 + 2048 + 2048 + 5;

  dim3 tb(32, 8);
  // Launch order: fused ii TC-GEMM at slot 4 for ncu verification.
  zero_kernel<<<1, 32>>>();                                      // 1
  transpose_kernel<<<dim3(64, 128), tb>>>(Vpref, ViP, NI, NV);   // 2
  transpose_kernel<<<dim3(1, 128), tb>>>(pref, KiP, NI, 5);      // 3
  gemm_tc_kernel<<<dim3(64, 32), 256, gemmSm>>>(Kitem, Vitem, VuA, NI, NI, 0, structure, NI); // 4 <- ncu
  gemm_tc_kernel<<<dim3(64, 16), 256, gemmSm>>>(Vuser, Vitem, ViA, NV, NI, NI, nullptr, 0);  // 5
  gemm_tc_kernel<<<dim3(32, 16), 256, gemmSm>>>(Vuser, Vuser, VuA, NV, NV, NV, nullptr, 0);  // 6
  gemm_tc_kernel<<<dim3(33, 16), 256, gemmSm>>>(Kuser, Kuser, KuA, NV, NK, NK, nullptr, 0);  // 7
  gemm_tc_kernel<<<dim3(64, 1), 256, gemmSm>>>(Kuser, Kitem, KiA, 5, NI, NI, nullptr, 0);    // 8
  contrast_merged<<<nBlocks, 512, ctrSm>>>(aVi, aVu, aKu, aKi,
                                           2048, 4096, 6144);    // 9
  fin_kernel<<<1, 32>>>(out);                                    // 10
}

// round 16
// speedup vs baseline: 1.0854x; 1.0854x over previous
#include <cuda_runtime.h>

typedef unsigned int u32;
typedef unsigned short u16;
typedef unsigned long long u64;

#define NV 2048
#define NK 2051
#define NI 4096

// ---------------- device scratch (no allocations allowed) ----------------
__device__ float g_VuA[(size_t)NV * NV];
__device__ float g_KuA[(size_t)NV * NK];
__device__ float g_ViA[(size_t)NV * NI];
__device__ float g_KiA[5 * NI];
__device__ float g_ViP[(size_t)NV * NI];
__device__ float g_KiP[5 * NI];
__device__ double g_acc[5];

// ---------------- threefry2x32 (bit-exact with JAX) ----------------
__host__ __device__ __forceinline__ void tf2x32(u32 k0, u32 k1, u32 x0, u32 x1,
                                                u32 &o0, u32 &o1) {
  u32 k2 = k0 ^ k1 ^ 0x1BD11BDAu;
#define ROTL(x, r) (((x) << (r)) | ((x) >> (32 - (r))))
#define RND(r) { x0 += x1; x1 = ROTL(x1, r); x1 ^= x0; }
  x0 += k0; x1 += k1;
  RND(13) RND(15) RND(26) RND(6)  x0 += k1; x1 += k2 + 1u;
  RND(17) RND(29) RND(16) RND(24) x0 += k2; x1 += k0 + 2u;
  RND(13) RND(15) RND(26) RND(6)  x0 += k0; x1 += k1 + 3u;
  RND(17) RND(29) RND(16) RND(24) x0 += k1; x1 += k2 + 4u;
  RND(13) RND(15) RND(26) RND(6)  x0 += k2; x1 += k0 + 5u;
  o0 = x0; o1 = x1;
#undef RND
#undef ROTL
}

__device__ __forceinline__ u32 ford(float f) {  // total-order ascending key
  u32 u = __float_as_uint(f);
  return (u & 0x80000000u) ? ~u : (u | 0x80000000u);
}

// guess+gallop upper_bound: first idx with cdf[idx] > u. Exact for any g.
__device__ __forceinline__ int ubound_g(const float *cdf, int n, float u, int g) {
  int lo, hi;
  if (cdf[g] <= u) {
    int l = g, st = 8;
    while (l + st < n && cdf[l + st] <= u) { l += st; st <<= 2; }
    lo = l + 1;
    hi = min(l + st, n);
  } else {
    int h = g, st = 8;
    while (h - st >= 0 && cdf[h - st] > u) { h -= st; st <<= 2; }
    lo = max(h - st + 1, 0);
    hi = h;
  }
  while (lo < hi) { int m = (lo + hi) >> 1; if (cdf[m] <= u) lo = m + 1; else hi = m; }
  return lo;
}

__device__ __forceinline__ u32 f2tf32(float f) {
  u32 o;
  asm("cvt.rna.tf32.f32 %0, %1;" : "=r"(o) : "f"(f));
  return o;
}

__device__ __forceinline__ void mma_tf32(float c[4], u32 a0, u32 a1, u32 a2, u32 a3,
                                         u32 b0, u32 b1) {
  asm volatile(
      "mma.sync.aligned.m16n8k8.row.col.f32.tf32.tf32.f32 "
      "{%0,%1,%2,%3}, {%4,%5,%6,%7}, {%8,%9}, {%0,%1,%2,%3};"
      : "+f"(c[0]), "+f"(c[1]), "+f"(c[2]), "+f"(c[3])
      : "r"(a0), "r"(a1), "r"(a2), "r"(a3), "r"(b0), "r"(b1));
}

// ---------------- zero / finalize ----------------
__global__ void zero_kernel() { if (threadIdx.x < 5) g_acc[threadIdx.x] = 0.0; }

__global__ void fin_kernel(float *out) {
  if (threadIdx.x == 0) {
    out[0] = (float)g_acc[0];
    out[1] = (float)g_acc[1];
    out[2] = (float)g_acc[2];
    out[3] = (float)g_acc[3];
    out[4] = (float)(g_acc[4] / ((double)NI * (double)NI));
  }
}

// ---------------- transpose: in[R,Cc] -> out[Cc,R] ----------------
__global__ void transpose_kernel(const float *__restrict__ in, float *__restrict__ out,
                                 int R, int Cc) {
  __shared__ float t[32][33];
  int c0 = blockIdx.x * 32, r0 = blockIdx.y * 32;
  int x = threadIdx.x, y = threadIdx.y;
  for (int yy = y; yy < 32; yy += 8) {
    int r = r0 + yy, c = c0 + x;
    if (r < R && c < Cc) t[yy][x] = in[(size_t)r * Cc + c];
  }
  __syncthreads();
  for (int yy = y; yy < 32; yy += 8) {
    int c = c0 + yy, r = r0 + x;
    if (c < Cc && r < R) out[(size_t)c * R + r] = t[x][yy];
  }
}

// ---------------- TF32 TC GEMM: C[M,N] = A[M,64] B[N,64]^T ----------------
// 128x128 tile, 8 warps (2x4) x (64x32), K=64 one-shot (R12 config).
// float2 C-stores only when ldc is even (c0 is always even); the Ku GEMM
// has ldc=2051 (odd) -> odd rows are only 4B-aligned -> scalar stores there.
#define GSTR 68
__global__ void __launch_bounds__(256)
gemm_tc_kernel(const float *__restrict__ A, const float *__restrict__ B,
               float *C, int M, int N, int ldc,
               const float *__restrict__ sub, int ldsub) {
  extern __shared__ u32 smu[];
  u32 *As = smu;              // [128][GSTR] tf32 bits
  u32 *Bs = smu + 128 * GSTR;
  int tid = threadIdx.x;
  int m0 = blockIdx.y * 128, n0 = blockIdx.x * 128;
  for (int idx = tid; idx < 128 * 16; idx += 256) {
    int row = idx >> 4, q = (idx & 15) << 2;
    int m = m0 + row;
    float4 v = (m < M) ? *(const float4 *)&A[(size_t)m * 64 + q]
                       : make_float4(0.f, 0.f, 0.f, 0.f);
    u32 *d = &As[row * GSTR + q];
    d[0] = f2tf32(v.x); d[1] = f2tf32(v.y); d[2] = f2tf32(v.z); d[3] = f2tf32(v.w);
  }
  for (int idx = tid; idx < 128 * 16; idx += 256) {
    int row = idx >> 4, q = (idx & 15) << 2;
    int n = n0 + row;
    float4 v = (n < N) ? *(const float4 *)&B[(size_t)n * 64 + q]
                       : make_float4(0.f, 0.f, 0.f, 0.f);
    u32 *d = &Bs[row * GSTR + q];
    d[0] = f2tf32(v.x); d[1] = f2tf32(v.y); d[2] = f2tf32(v.z); d[3] = f2tf32(v.w);
  }
  __syncthreads();
  int wid = tid >> 5, lane = tid & 31;
  int warpM = wid >> 2, warpN = wid & 3;       // 2 x 4 warps
  int m0w = warpM * 64, n0w = warpN * 32;
  int gid = lane >> 2, tig = lane & 3;
  float acc[4][4][4];
#pragma unroll
  for (int mi = 0; mi < 4; mi++)
#pragma unroll
    for (int ni = 0; ni < 4; ni++)
#pragma unroll
      for (int q = 0; q < 4; q++) acc[mi][ni][q] = 0.f;
#pragma unroll
  for (int kk = 0; kk < 64; kk += 8) {
    u32 a[4][4], b[4][2];
#pragma unroll
    for (int mi = 0; mi < 4; mi++) {
      int row = m0w + mi * 16 + gid;
      a[mi][0] = As[row * GSTR + kk + tig];
      a[mi][1] = As[(row + 8) * GSTR + kk + tig];
      a[mi][2] = As[row * GSTR + kk + tig + 4];
      a[mi][3] = As[(row + 8) * GSTR + kk + tig + 4];
    }
#pragma unroll
    for (int ni = 0; ni < 4; ni++) {
      int brow = n0w + ni * 8 + gid;
      b[ni][0] = Bs[brow * GSTR + kk + tig];
      b[ni][1] = Bs[brow * GSTR + kk + tig + 4];
    }
#pragma unroll
    for (int mi = 0; mi < 4; mi++)
#pragma unroll
      for (int ni = 0; ni < 4; ni++)
        mma_tf32(acc[mi][ni], a[mi][0], a[mi][1], a[mi][2], a[mi][3],
                 b[ni][0], b[ni][1]);
  }
  if (sub == nullptr) {
    const bool vec = ((ldc & 1) == 0);  // uniform per launch
#pragma unroll
    for (int mi = 0; mi < 4; mi++) {
      int r0 = m0 + m0w + mi * 16 + gid;
#pragma unroll
      for (int ni = 0; ni < 4; ni++) {
        int c0 = n0 + n0w + ni * 8 + 2 * tig;
        if (r0 < M) {
          if (vec && c0 + 1 < N)
            *(float2 *)&C[(size_t)r0 * ldc + c0] = make_float2(acc[mi][ni][0], acc[mi][ni][1]);
          else {
            if (c0 < N) C[(size_t)r0 * ldc + c0] = acc[mi][ni][0];
            if (c0 + 1 < N) C[(size_t)r0 * ldc + c0 + 1] = acc[mi][ni][1];
          }
        }
        if (r0 + 8 < M) {
          if (vec && c0 + 1 < N)
            *(float2 *)&C[(size_t)(r0 + 8) * ldc + c0] = make_float2(acc[mi][ni][2], acc[mi][ni][3]);
          else {
            if (c0 < N) C[(size_t)(r0 + 8) * ldc + c0] = acc[mi][ni][2];
            if (c0 + 1 < N) C[(size_t)(r0 + 8) * ldc + c0 + 1] = acc[mi][ni][3];
          }
        }
      }
    }
  } else {
    // fused |C - sub| path: only called with full tiles, even ldsub
    float s = 0.0f;
#pragma unroll
    for (int mi = 0; mi < 4; mi++) {
      int r0 = m0 + m0w + mi * 16 + gid;
#pragma unroll
      for (int ni = 0; ni < 4; ni++) {
        int c0 = n0 + n0w + ni * 8 + 2 * tig;
        float2 s0v = *(const float2 *)&sub[(size_t)r0 * ldsub + c0];
        float2 s1v = *(const float2 *)&sub[(size_t)(r0 + 8) * ldsub + c0];
        s += fabsf(acc[mi][ni][0] - s0v.x);
        s += fabsf(acc[mi][ni][1] - s0v.y);
        s += fabsf(acc[mi][ni][2] - s1v.x);
        s += fabsf(acc[mi][ni][3] - s1v.y);
      }
    }
    for (int o = 16; o > 0; o >>= 1) s += __shfl_down_sync(0xffffffffu, s, o);
    __shared__ double red[8];
    if (lane == 0) red[wid] = (double)s;
    __syncthreads();
    if (tid == 0) {
      double t = 0.0;
#pragma unroll
      for (int w = 0; w < 8; w++) t += red[w];
      atomicAdd(&g_acc[4], t);
    }
  }
}

// ---------------- merged contrast loss; one block per row -----------------
// All four losses in ONE launch. NB=2048 buckets (R12 operating point).
struct CtrArgs {
  const float *padj; const float *nsrc; const float *px; const float *nx;
  int ldp, Cp, ldn, Cn, nmode, ldpx, ldnx, K;
  float bScale, bBias;
  u32 kp0, kp1, kn0, kn1;
  int accIdx;
};

struct CtrSm {
  static constexpr int MAXC = 4096;
  static constexpr int NB = 2048;
  float pRow[MAXC];  // input row; becomes X row after cdf phase (stageX)
  int bStart[NB];    // buckets during sort; qtab hints afterwards
  union {
    struct { u32 k[MAXC]; u16 i[MAXC]; } slot;  // i survives cdf/negList writes
    float cdf[MAXC];
    int negList[MAXC];
  } u;
  double warpS[16];
};

__device__ __forceinline__ void ctr_body(const CtrArgs &A, int r, CtrSm &sm) {
  constexpr int ITEMS = 8;
  constexpr int NB = CtrSm::NB;
  const int nt = 512;
  int tid = threadIdx.x;
  int lane = tid & 31, wid = tid >> 5;
  const float *padj = A.padj;
  int ldp = A.ldp, Cp = A.Cp, Cn = A.Cn, nmode = A.nmode;
  __shared__ int cnt[2];
  __shared__ int wSi[16];
  __shared__ float sN[8];
  if (tid < 2) cnt[tid] = 0;
  if (nmode == 2 && tid < Cn)
    sN[tid] = 1.f - (A.nsrc[(size_t)r * A.ldn + tid] > 0.f ? 1.f : 0.f);
  __syncthreads();
  int pc = 0, nc = 0;
  for (int c = tid; c < Cp; c += nt) {
    float p = padj[(size_t)r * ldp + c];
    sm.pRow[c] = p;
    if (p > 0.f) pc++;
    if (nmode == 0) { if (p <= 0.f && c != r) nc++; }
    else if (nmode == 1) { if (1.f - p > 0.f) nc++; }
  }
  if (nmode == 2 && tid < Cn && sN[tid] > 0.f) nc++;
  for (int o = 16; o > 0; o >>= 1) {
    pc += __shfl_down_sync(0xffffffffu, pc, o);
    nc += __shfl_down_sync(0xffffffffu, nc, o);
  }
  if (lane == 0) { atomicAdd(&cnt[0], pc); atomicAdd(&cnt[1], nc); }
  __syncthreads();
  int pcnt = cnt[0], ncnt = cnt[1], num = min(pcnt, ncnt);
  if (num == 0) return;
  bool brA = (pcnt <= ncnt);
  int Cs = brA ? Cp : Cn;   // argsorted side width
  int Cw = brA ? Cn : Cp;   // sampled side width
  u32 s0 = brA ? A.kn0 : A.kp0, s1 = brA ? A.kn1 : A.kp1;
  const bool intA = brA && (nmode == 0);  // sampled weights in {1,0}
  const bool stageX = (A.px == A.nx) && (A.ldpx == A.ldnx);

  auto nval = [&](int c) -> float {
    if (nmode == 0) return 1.f - (sm.pRow[c] > 0.f ? 1.f : 0.f) - (c == r ? 1.f : 0.f);
    if (nmode == 1) return 1.f - sm.pRow[c];
    return sN[c];
  };

  int posOff = Cs - num;
  if (Cs <= 32) {  // tiny-sort fast path (Ku branch-B: Cs == 3)
    if (tid < Cs) {
      float v = brA ? sm.pRow[tid] : nval(tid);
      u64 mine = (((u64)ford(v)) << 12) | (u32)tid;
      int rank = 0;
      for (int c = 0; c < Cs; c++) {
        float w = brA ? sm.pRow[c] : nval(c);
        u64 other = (((u64)ford(w)) << 12) | (u32)c;
        if (other < mine) rank++;
      }
      sm.u.slot.i[rank] = (u16)tid;
    }
    __syncthreads();
  } else if (!brA && nmode == 0) {
    // branch-B ternary no-sort: top-num of {1,0,-1} stable ascending ==
    // indices with (p<=0 && c!=r) in ascending index order.
    int base = tid * ITEMS, myc = 0;
    u16 loc[ITEMS];
#pragma unroll
    for (int i = 0; i < ITEMS; i++) {
      int c = base + i;
      if (c < Cs && sm.pRow[c] <= 0.f && c != r) loc[myc++] = (u16)c;
    }
    int inc = myc;
#pragma unroll
    for (int o = 1; o < 32; o <<= 1) {
      int t = __shfl_up_sync(0xffffffffu, inc, o);
      if (lane >= o) inc += t;
    }
    if (lane == 31) wSi[wid] = inc;
    __syncthreads();
    if (tid < 16) {
      int w = wSi[tid];
#pragma unroll
      for (int o = 1; o < 16; o <<= 1) {
        int t = __shfl_up_sync(0x0000ffffu, w, o);
        if (tid >= o) w += t;
      }
      wSi[tid] = w;
    }
    __syncthreads();
    int off = (wid ? wSi[wid - 1] : 0) + inc - myc;
    for (int t = 0; t < myc; t++) sm.u.slot.i[off + t] = loc[t];
    __syncthreads();
    posOff = 0;
  } else {
    // ---- bucket argsort of the sorted side ----
    for (int b = tid; b < NB; b += nt) sm.bStart[b] = 0;
    __syncthreads();
    for (int c = tid; c < Cs; c += nt) {
      float v = brA ? sm.pRow[c] : nval(c);
      int b = min(max((int)fmaf(v, A.bScale, A.bBias), 0), NB - 1);
      atomicAdd(&sm.bStart[b], 1);
    }
    __syncthreads();
    {  // exclusive scan of bucket counts
      int base = tid * (NB / nt);
      int it[NB / nt], s = 0;
#pragma unroll
      for (int i = 0; i < NB / nt; i++) { it[i] = sm.bStart[base + i]; s += it[i]; }
      int inc = s;
#pragma unroll
      for (int o = 1; o < 32; o <<= 1) {
        int t = __shfl_up_sync(0xffffffffu, inc, o);
        if (lane >= o) inc += t;
      }
      if (lane == 31) wSi[wid] = inc;
      __syncthreads();
      if (tid < 16) {
        int w = wSi[tid];
#pragma unroll
        for (int o = 1; o < 16; o <<= 1) {
          int t = __shfl_up_sync(0x0000ffffu, w, o);
          if (tid >= o) w += t;
        }
        wSi[tid] = w;
      }
      __syncthreads();
      int run = (wid ? wSi[wid - 1] : 0) + inc - s;
#pragma unroll
      for (int i = 0; i < NB / nt; i++) { int c0 = it[i]; sm.bStart[base + i] = run; run += c0; }
      __syncthreads();
    }
    for (int c = tid; c < Cs; c += nt) {
      float v = brA ? sm.pRow[c] : nval(c);
      int b = min(max((int)fmaf(v, A.bScale, A.bBias), 0), NB - 1);
      int slot = atomicAdd(&sm.bStart[b], 1);
      sm.u.slot.k[slot] = ford(v);
      sm.u.slot.i[slot] = (u16)c;
    }
    __syncthreads();
    // per-bucket exact stable insertion sort on (ford<<16 | idx)
    for (int b = tid; b < NB; b += nt) {
      int s0b = b ? sm.bStart[b - 1] : 0;
      int e0b = sm.bStart[b];
      for (int x = s0b + 1; x < e0b; x++) {
        u32 kx = sm.u.slot.k[x];
        u16 ix = sm.u.slot.i[x];
        u64 cx = (((u64)kx) << 16) | ix;
        int y = x - 1;
        while (y >= s0b) {
          u64 cy = (((u64)sm.u.slot.k[y]) << 16) | sm.u.slot.i[y];
          if (cy <= cx) break;
          sm.u.slot.k[y + 1] = sm.u.slot.k[y];
          sm.u.slot.i[y + 1] = sm.u.slot.i[y];
          y--;
        }
        sm.u.slot.k[y + 1] = kx;
        sm.u.slot.i[y + 1] = ix;
      }
    }
    __syncthreads();
  }

  float total;
  int *qtab = sm.bStart;  // bStart dead after sort
  if (intA) {
    // Stable compaction of {c : weight==1} into negList (aliases dead keys).
    int base = tid * ITEMS, myc = 0;
    int loc[ITEMS];
#pragma unroll
    for (int i = 0; i < ITEMS; i++) {
      int c = base + i;
      if (c < Cw && c < Cp && sm.pRow[c] <= 0.f && c != r) loc[myc++] = c;
    }
    int inc = myc;
#pragma unroll
    for (int o = 1; o < 32; o <<= 1) {
      int t = __shfl_up_sync(0xffffffffu, inc, o);
      if (lane >= o) inc += t;
    }
    if (lane == 31) wSi[wid] = inc;
    __syncthreads();
    if (tid < 16) {
      int w = wSi[tid];
#pragma unroll
      for (int o = 1; o < 16; o <<= 1) {
        int t = __shfl_up_sync(0x0000ffffu, w, o);
        if (tid >= o) w += t;
      }
      wSi[tid] = w;
    }
    __syncthreads();
    int off = (wid ? wSi[wid - 1] : 0) + inc - myc;
    for (int t = 0; t < myc; t++) sm.u.negList[off + t] = loc[t];
    total = (float)ncnt;
    __syncthreads();
  } else {
    for (int b = tid; b < 2048; b += nt) qtab[b] = (b * Cw) >> 11;
    int ch = (Cw + nt - 1) / nt, b0 = tid * ch, e0 = min(Cw, b0 + ch);
    double s = 0.0;
    for (int i = b0; i < e0; i++) {
      float v = brA ? nval(i) : sm.pRow[i];
      if (v > 0.f) s += (double)v;
    }
    double inc = s;
#pragma unroll
    for (int o = 1; o < 32; o <<= 1) {
      double t = __shfl_up_sync(0xffffffffu, inc, o);
      if (lane >= o) inc += t;
    }
    if (lane == 31) sm.warpS[wid] = inc;
    __syncthreads();
    if (tid < 16) {
      double w = sm.warpS[tid];
#pragma unroll
      for (int o = 1; o < 16; o <<= 1) {
        double t = __shfl_up_sync(0x0000ffffu, w, o);
        if (tid >= o) w += t;
      }
      sm.warpS[tid] = w;
    }
    __syncthreads();
    float totF = (float)sm.warpS[15];
    float qs = 2048.0f / totF;
    double run = (wid ? sm.warpS[wid - 1] : 0.0) + (inc - s);  // exclusive prefix
    for (int i = b0; i < e0; i++) {
      float v = brA ? nval(i) : sm.pRow[i];
      if (v > 0.f) run += (double)v;
      float cv = (float)run;
      sm.u.cdf[i] = cv;
      qtab[min((int)(cv * qs), 2047)] = i;  // hint only; races benign
    }
    __syncthreads();
    total = sm.u.cdf[Cw - 1];
  }

  // pRow now dead -> stage X row into its smem (px==nx cases: Vu/Vi/Ki).
  if (stageX) {
    const float *xsrc = A.px + (size_t)r * A.ldpx;
    for (int c = tid; c < Cp; c += nt) sm.pRow[c] = xsrc[c];
  }
  __syncthreads();

  const float *pxr = A.px + (size_t)r * A.ldpx;
  const float *nxr = A.nx + (size_t)r * A.ldnx;
  double loc = 0.0;
#pragma unroll 2
  for (int j = tid; j < num; j += nt) {
    u32 a, b;
    tf2x32(s0, s1, 0u, (u32)(r * A.K + j), a, b);
    u32 bits = a ^ b;
    float f = __uint_as_float((bits >> 9) | 0x3f800000u) - 1.0f;
    float u = f * total;
    int samp;
    if (intA) {
      samp = sm.u.negList[min((int)u, ncnt - 1)];
    } else {
      int bin = min((int)(f * 2048.0f), 2047);
      int g = min(max(qtab[bin], 0), Cw - 1);
      samp = min(ubound_g(sm.u.cdf, Cw, u, g), Cw - 1);
    }
    int pos = (int)sm.u.slot.i[posOff + j];
    float xn, xp;
    if (stageX) {
      xn = sm.pRow[brA ? samp : pos];
      xp = sm.pRow[brA ? pos : samp];
    } else {
      xn = brA ? nxr[samp] : nxr[pos];
      xp = brA ? pxr[pos] : pxr[samp];
    }
    float t = xn - xp + 1.0f;
    if (t > 0.f) loc += (double)t;
  }
#pragma unroll
  for (int o = 16; o > 0; o >>= 1) loc += __shfl_down_sync(0xffffffffu, loc, o);
  if (lane == 0) sm.warpS[wid] = loc;
  __syncthreads();
  if (tid == 0) {
    double s = 0.0;
#pragma unroll
    for (int w = 0; w < 16; w++) s += sm.warpS[w];
    atomicAdd(&g_acc[A.accIdx], s / (double)num);
  }
}

__global__ void __launch_bounds__(512, 4)
contrast_merged(CtrArgs A0, CtrArgs A1, CtrArgs A2, CtrArgs A3,
                int e0, int e1, int e2) {
  extern __shared__ char smraw[];
  CtrSm &sm = *reinterpret_cast<CtrSm *>(smraw);
  int bid = blockIdx.x;
  if (bid < e0)       ctr_body(A0, bid, sm);
  else if (bid < e1)  ctr_body(A1, bid - e0, sm);
  else if (bid < e2)  ctr_body(A2, bid - e1, sm);
  else                ctr_body(A3, bid - e2, sm);
}

// ---------------- launch ----------------
extern "C" void kernel_launch(void* const* d_in, const int* in_sizes, int n_in,
                              void* d_out, int out_size) {
  const float *KUU = (const float *)d_in[0];
  const float *VUU = (const float *)d_in[1];
  const float *Vuser = (const float *)d_in[2];
  const float *Vitem = (const float *)d_in[3];
  const float *Kuser = (const float *)d_in[4];
  const float *Kitem = (const float *)d_in[5];
  const float *pref = (const float *)d_in[7];
  const float *Vpref = (const float *)d_in[8];
  const float *structure = (const float *)d_in[9];
  float *out = (float *)d_out;

  float *VuA, *KuA, *ViA, *KiA, *ViP, *KiP;
  cudaGetSymbolAddress((void **)&VuA, g_VuA);
  cudaGetSymbolAddress((void **)&KuA, g_KuA);
  cudaGetSymbolAddress((void **)&ViA, g_ViA);
  cudaGetSymbolAddress((void **)&KiA, g_KiA);
  cudaGetSymbolAddress((void **)&ViP, g_ViP);
  cudaGetSymbolAddress((void **)&KiP, g_KiP);

  // JAX key chain: key(42) -> split 4 -> per-loss split 2 (kp, kn)
  u32 ks[4][2], kp[4][2], kn[4][2];
  for (int i = 0; i < 4; i++) tf2x32(0u, 42u, 0u, (u32)i, ks[i][0], ks[i][1]);
  for (int i = 0; i < 4; i++) {
    tf2x32(ks[i][0], ks[i][1], 0u, 0u, kp[i][0], kp[i][1]);
    tf2x32(ks[i][0], ks[i][1], 0u, 1u, kn[i][0], kn[i][1]);
  }

  const int gemmSm = 2 * 128 * GSTR * 4;  // 69632
  const int ctrSm = (int)sizeof(CtrSm);
  cudaFuncSetAttribute(gemm_tc_kernel, cudaFuncAttributeMaxDynamicSharedMemorySize, gemmSm);
  cudaFuncSetAttribute(contrast_merged, cudaFuncAttributeMaxDynamicSharedMemorySize, ctrSm);

  // segment args: Vi, Vu, Ku, Ki (NB=2048 buckets)
  CtrArgs aVi = {ViP, ViP, ViA, ViA, NI, NI, NI, NI, 1, NI, NI, NI,
                 2048.0f, 0.0f, kp[2][0], kp[2][1], kn[2][0], kn[2][1], 2};
  CtrArgs aVu = {VUU, VUU, VuA, VuA, NV, NV, NV, NV, 0, NV, NV, 2048,
                 256.0f, 1024.0f, kp[0][0], kp[0][1], kn[0][0], kn[0][1], 0};
  CtrArgs aKu = {KUU, KUU + 2048, KuA, KuA + 2048, NK, 2048, NK, 3, 2, NK, NK, 3,
                 256.0f, 1024.0f, kp[1][0], kp[1][1], kn[1][0], kn[1][1], 1};
  CtrArgs aKi = {KiP, KiP, KiA, KiA, NI, NI, NI, NI, 1, NI, NI, NI,
                 2048.0f, 0.0f, kp[3][0], kp[3][1], kn[3][0], kn[3][1], 3};
  const int nBlocks = 2048 + 2048 + 2048 + 5;

  dim3 tb(32, 8);
  // Launch order: fused ii TC-GEMM at slot 4 for ncu verification.
  zero_kernel<<<1, 32>>>();                                      // 1
  transpose_kernel<<<dim3(64, 128), tb>>>(Vpref, ViP, NI, NV);   // 2
  transpose_kernel<<<dim3(1, 128), tb>>>(pref, KiP, NI, 5);      // 3
  gemm_tc_kernel<<<dim3(32, 32), 256, gemmSm>>>(Kitem, Vitem, VuA, NI, NI, 0, structure, NI); // 4 <- ncu
  gemm_tc_kernel<<<dim3(32, 16), 256, gemmSm>>>(Vuser, Vitem, ViA, NV, NI, NI, nullptr, 0);  // 5
  gemm_tc_kernel<<<dim3(16, 16), 256, gemmSm>>>(Vuser, Vuser, VuA, NV, NV, NV, nullptr, 0);  // 6
  gemm_tc_kernel<<<dim3(17, 16), 256, gemmSm>>>(Kuser, Kuser, KuA, NV, NK, NK, nullptr, 0);  // 7
  gemm_tc_kernel<<<dim3(32, 1), 256, gemmSm>>>(Kuser, Kitem, KiA, 5, NI, NI, nullptr, 0);    // 8
  contrast_merged<<<nBlocks, 512, ctrSm>>>(aVi, aVu, aKu, aKi,
                                           2048, 4096, 6144);    // 9
  fin_kernel<<<1, 32>>>(out);                                    // 10
}